// round 7
// baseline (speedup 1.0000x reference)
#include <cuda_runtime.h>

#define FULL 0xFFFFFFFFu
#define NUM_E 256
#define TOPK 8

__device__ __forceinline__ float sigmoidf_fast(float x) {
    return __fdividef(1.0f, 1.0f + __expf(-x));
}

__global__ void __launch_bounds__(256)
moe_route_kernel(const float* __restrict__ logits,
                 const float* __restrict__ bias,
                 float* __restrict__ out_idx,   // indices stored as float32 values
                 float* __restrict__ out_w,
                 int T)
{
    const int lane = threadIdx.x & 31;
    const int seg  = lane >> 4;           // 0 or 1: token-half of the warp
    const int sl   = lane & 15;           // lane within segment
    const int wgl  = (int)((blockIdx.x * blockDim.x + threadIdx.x) >> 5);
    const int tok  = 2 * wgl + seg;
    if (tok >= T) return;                 // uniform per warp (T even)

    const unsigned smask = 0xFFFFu << (seg << 4);

    // lane covers 16 experts: float4 vectors sl, sl+16, sl+32, sl+48 of its row
    const float4* row4 = reinterpret_cast<const float4*>(logits) + (size_t)tok * (NUM_E / 4);
    const float4* b4   = reinterpret_cast<const float4*>(bias);

    // ---- FAST PATH keys ----
    // key = raw float bits of (sigmoid+bias), low 8 bits = (j<<4)|sl  (unique in segment).
    // Signed-int compare: correct for positive keys; top-9 keys are always positive
    // (~half the biases are positive => 9th biased score > 0). Any 24-bit prefix tie
    // among adjacent winners -> exact fallback.
    int k[16];
#pragma unroll
    for (int i = 0; i < 4; i++) {
        float4 x = row4[sl + 16 * i];
        float4 b = __ldg(b4 + sl + 16 * i);
        float s0 = sigmoidf_fast(x.x) + b.x;
        float s1 = sigmoidf_fast(x.y) + b.y;
        float s2 = sigmoidf_fast(x.z) + b.z;
        float s3 = sigmoidf_fast(x.w) + b.w;
        k[4*i+0] = (int)((__float_as_uint(s0) & 0xFFFFFF00u) | (unsigned)(((4*i+0) << 4) | sl));
        k[4*i+1] = (int)((__float_as_uint(s1) & 0xFFFFFF00u) | (unsigned)(((4*i+1) << 4) | sl));
        k[4*i+2] = (int)((__float_as_uint(s2) & 0xFFFFFF00u) | (unsigned)(((4*i+2) << 4) | sl));
        k[4*i+3] = (int)((__float_as_uint(s3) & 0xFFFFFF00u) | (unsigned)(((4*i+3) << 4) | sl));
    }

    // ---- per-lane top-4 of 16, descending ----
#define CED(a, b) { int hi = max(k[a], k[b]); int lo = min(k[a], k[b]); k[a] = hi; k[b] = lo; }
    // sort each group of 4 desc (5 CE each)
    CED(0,1)  CED(2,3)  CED(0,2)  CED(1,3)  CED(1,2)
    CED(4,5)  CED(6,7)  CED(4,6)  CED(5,7)  CED(5,6)
    CED(8,9)  CED(10,11) CED(8,10) CED(9,11) CED(9,10)
    CED(12,13) CED(14,15) CED(12,14) CED(13,15) CED(13,14)
#undef CED
#define MERGE4(d0,d1,d2,d3, a0,a1,a2,a3, b0,b1,b2,b3) {            \
        int m0 = max(a0, b3), m1 = max(a1, b2);                    \
        int m2 = max(a2, b1), m3 = max(a3, b0);                    \
        int p0 = max(m0, m2), p2 = min(m0, m2);                    \
        int p1 = max(m1, m3), p3 = min(m1, m3);                    \
        d0 = max(p0, p1); d1 = min(p0, p1);                        \
        d2 = max(p2, p3); d3 = min(p2, p3); }
    int a0,a1,a2,a3, b0,b1,b2,b3, t0,t1,t2,t3;
    MERGE4(a0,a1,a2,a3, k[0],k[1],k[2],k[3],   k[4],k[5],k[6],k[7])
    MERGE4(b0,b1,b2,b3, k[8],k[9],k[10],k[11], k[12],k[13],k[14],k[15])
    MERGE4(t0,t1,t2,t3, a0,a1,a2,a3, b0,b1,b2,b3)
#undef MERGE4

    // ---- 8 extraction rounds + 9th REDUX (verification), per 16-lane segment ----
    // One REDUX instruction serves both segments. Shift chain via float selects.
    // t3 never refilled: >4 consumed from one lane => adjacent stale dup => fallback.
    float f0 = __int_as_float(t0), f1 = __int_as_float(t1);
    float f2 = __int_as_float(t2), f3 = __int_as_float(t3);
    int w[9];
#pragma unroll
    for (int r = 0; r < TOPK; r++) {
        int wb = __reduce_max_sync(smask, __float_as_int(f0));
        w[r] = wb;
        bool own = (__float_as_int(f0) == wb);   // unique owner (fld embedded)
        f0 = own ? f1 : f0;
        f1 = own ? f2 : f1;
        f2 = own ? f3 : f2;
    }
    w[8] = __reduce_max_sync(smask, __float_as_int(f0));

    // verify: exact iff all adjacent winners (incl. 9th) differ in upper 24 bits
    unsigned mn = 0xFFFFFFFFu;
#pragma unroll
    for (int r = 0; r < 8; r++)
        mn = min(mn, (unsigned)w[r] ^ (unsigned)w[r + 1]);
    bool ok = (mn >= 256u);                       // uniform within segment

    if (ok) {
        if (sl < TOPK) {
            // keep = w[sl] via select tree (w[] are segment-wide REDUX results)
            int s0 = (sl & 1) ? w[1] : w[0];
            int s1 = (sl & 1) ? w[3] : w[2];
            int s2 = (sl & 1) ? w[5] : w[4];
            int s3 = (sl & 1) ? w[7] : w[6];
            int u0 = (sl & 2) ? s1 : s0;
            int u1 = (sl & 2) ? s3 : s2;
            unsigned kk = (unsigned)((sl & 4) ? u1 : u0);

            unsigned jj  = (kk >> 4) & 15u;
            unsigned sl2 = kk & 15u;
            int g = 4 * (int)sl2 + 64 * (int)(jj >> 2) + (int)(jj & 3u);

            float x = __ldg(logits + (size_t)tok * NUM_E + g);
            float wgt = sigmoidf_fast(x);
            float sum = wgt;
            unsigned emask = 0xFFu << (seg << 4);
#pragma unroll
            for (int off = 4; off; off >>= 1)
                sum += __shfl_xor_sync(emask, sum, off);
            float wn = wgt * __fdividef(1.0f, sum + 1e-20f);

            out_idx[(size_t)tok * TOPK + sl] = (float)g;
            out_w [(size_t)tok * TOPK + sl] = wn;
        }
    } else if (sl == 0) {
        // ---- EXACT SERIAL FALLBACK (rare, ~0.25% of segments; row is L1-hot) ----
        // insertion top-8 with strict '>' : lowest expert index wins ties (JAX order)
        const float* rr = logits + (size_t)tok * NUM_E;
        float v[8];
        int   gi[8];
#pragma unroll
        for (int r = 0; r < 8; r++) { v[r] = -3.4e38f; gi[r] = 0; }
        for (int e = 0; e < NUM_E; e++) {
            float key = sigmoidf_fast(__ldg(rr + e)) + __ldg(bias + e);
            if (key > v[7]) {
                v[7] = key; gi[7] = e;
#pragma unroll
                for (int r = 7; r > 0; r--) {
                    if (v[r] > v[r-1]) {
                        float tv = v[r]; v[r] = v[r-1]; v[r-1] = tv;
                        int   tg = gi[r]; gi[r] = gi[r-1]; gi[r-1] = tg;
                    }
                }
            }
        }
        float wv[8];
        float sum = 0.0f;
#pragma unroll
        for (int r = 0; r < 8; r++) { wv[r] = sigmoidf_fast(__ldg(rr + gi[r])); sum += wv[r]; }
        float inv = __fdividef(1.0f, sum + 1e-20f);
#pragma unroll
        for (int r = 0; r < 8; r++) {
            out_idx[(size_t)tok * TOPK + r] = (float)gi[r];
            out_w [(size_t)tok * TOPK + r] = wv[r] * inv;
        }
    }
}

extern "C" void kernel_launch(void* const* d_in, const int* in_sizes, int n_in,
                              void* d_out, int out_size)
{
    const float* logits = (const float*)d_in[0];
    const float* bias   = (const float*)d_in[1];
    int T = in_sizes[0] / NUM_E;

    float* out_idx = (float*)d_out;
    float* out_w   = (float*)d_out + (size_t)T * TOPK;

    // 2 tokens per warp, 8 warps per block => 16 tokens per block
    const int threads = 256;
    const int tok_per_block = 16;
    const int blocks = (T + tok_per_block - 1) / tok_per_block;
    moe_route_kernel<<<blocks, threads>>>(logits, bias, out_idx, out_w, T);
}

// round 8
// speedup vs baseline: 1.6169x; 1.6169x over previous
#include <cuda_runtime.h>

#define FULL 0xFFFFFFFFu
#define NUM_E 256
#define TOPK 8

// monotonic float -> u32 key (fallback path only)
__device__ __forceinline__ unsigned f2key(float f) {
    unsigned u = __float_as_uint(f);
    return u ^ ((unsigned)((int)u >> 31) | 0x80000000u);
}
__device__ __forceinline__ float sigmoidf_fast(float x) {
    return __fdividef(1.0f, 1.0f + __expf(-x));
}

__global__ void __launch_bounds__(256)
moe_route_kernel(const float* __restrict__ logits,
                 const float* __restrict__ bias,
                 float* __restrict__ out_idx,   // indices stored as float32 values
                 float* __restrict__ out_w,
                 int T)
{
    const int lane = threadIdx.x & 31;
    const int tok  = (int)((blockIdx.x * blockDim.x + threadIdx.x) >> 5);
    if (tok >= T) return;   // tok uniform per warp

    // coalesced row load: lane l covers experts {4l..4l+3, 128+4l..128+4l+3}
    const float4* row = reinterpret_cast<const float4*>(logits) + (size_t)tok * (NUM_E / 4);
    float4 x0 = row[lane];
    float4 x1 = row[lane + 32];
    const float4* b4 = reinterpret_cast<const float4*>(bias);
    float4 bb0 = __ldg(b4 + lane);
    float4 bb1 = __ldg(b4 + lane + 32);

    // ---- FAST PATH ----
    // key = raw float bits of (sigmoid+bias), low 8 bits replaced by (j<<5)|lane.
    // Signed-int compare: positives ordered correctly; top-9 keys are always
    // positive (~half the biases are positive => 9th biased score >> 0).
    // Unique keys (fld). Any 24-bit-prefix tie among adjacent winners -> fallback.
    int k[8];
    {
        float xs[8] = {x0.x, x0.y, x0.z, x0.w, x1.x, x1.y, x1.z, x1.w};
        float bs[8] = {bb0.x, bb0.y, bb0.z, bb0.w, bb1.x, bb1.y, bb1.z, bb1.w};
#pragma unroll
        for (int j = 0; j < 8; j++) {
            float s = sigmoidf_fast(xs[j]);
            unsigned ub  = __float_as_uint(s + bs[j]);
            unsigned fld = ((unsigned)j << 5) | (unsigned)lane;
            k[j] = (int)((ub & 0xFFFFFF00u) | fld);
        }
    }

    // ---- top-3-of-8 per lane, descending ----
#define CED(a, b) { int hi = max(k[a], k[b]); int lo = min(k[a], k[b]); k[a] = hi; k[b] = lo; }
    CED(0,1) CED(2,3) CED(0,2) CED(1,3) CED(1,2)     // sort k0..k3 desc
    CED(4,5) CED(6,7) CED(4,6) CED(5,7) CED(5,6)     // sort k4..k7 desc
#undef CED
    // top-3 of two sorted-4 lists: candidates c_i = max(a_i, b_{2-i})
    int c0 = max(k[0], k[6]);
    int c1 = max(k[1], k[5]);
    int c2 = max(k[2], k[4]);
    // sort 3 desc: (0,1)(0,2)(1,2)
    { int a = c0, b = c1; c0 = max(a, b); c1 = min(a, b); }
    { int a = c0, b = c2; c0 = max(a, b); c2 = min(a, b); }
    { int a = c1, b = c2; c1 = max(a, b); c2 = min(a, b); }

    // ---- 8 extraction rounds + 9th REDUX (verification) ----
    // 2-deep shift chain via float-bitcast selects. c2 never refilled: a lane's
    // 4th win re-emits its 3rd value => adjacent duplicate in w[] => fallback.
    float f0 = __int_as_float(c0), f1 = __int_as_float(c1), f2 = __int_as_float(c2);
    int w[9];
#pragma unroll
    for (int r = 0; r < TOPK; r++) {
        int wb = __reduce_max_sync(FULL, __float_as_int(f0));
        w[r] = wb;
        bool own = (__float_as_int(f0) == wb);   // unique owner (fld embedded)
        f0 = own ? f1 : f0;
        f1 = own ? f2 : f1;
    }
    w[8] = __reduce_max_sync(FULL, __float_as_int(f0));

    // verify: exact iff all adjacent winners (incl. 9th) differ in upper 24 bits
    unsigned mn = 0xFFFFFFFFu;
#pragma unroll
    for (int r = 0; r < 8; r++)
        mn = min(mn, (unsigned)w[r] ^ (unsigned)w[r + 1]);
    bool ok = (mn >= 256u);           // warp-uniform

    int g = 0;
    if (ok) {
        // keep = w[lane] for lanes 0..7 via select tree (REDUX broadcast values)
        int s0 = (lane & 1) ? w[1] : w[0];
        int s1 = (lane & 1) ? w[3] : w[2];
        int s2 = (lane & 1) ? w[5] : w[4];
        int s3 = (lane & 1) ? w[7] : w[6];
        int u0 = (lane & 2) ? s1 : s0;
        int u1 = (lane & 2) ? s3 : s2;
        int keep = (lane & 4) ? u1 : u0;

        unsigned kk = (unsigned)keep;
        unsigned jj = (kk >> 5) & 7u;
        unsigned sl = kk & 31u;
        g = 4 * (int)sl + (int)jj + ((jj & 4u) ? 124 : 0);
    } else {
        // ---- EXACT FALLBACK (rare, ~0.4%): full-precision keys, proven path ----
        float4 y0 = row[lane];        // L1/L2-hot reloads
        float4 y1 = row[lane + 32];
        float4 cb0 = __ldg(b4 + lane);
        float4 cb1 = __ldg(b4 + lane + 32);
        float ys[8] = {y0.x, y0.y, y0.z, y0.w, y1.x, y1.y, y1.z, y1.w};
        float cs[8] = {cb0.x, cb0.y, cb0.z, cb0.w, cb1.x, cb1.y, cb1.z, cb1.w};

        unsigned fk[8];
        unsigned pj[8];
#pragma unroll
        for (int j = 0; j < 8; j++) {
            float s = sigmoidf_fast(ys[j]);
            fk[j] = f2key(s + cs[j]);
            pj[j] = (unsigned)j;
        }
#define CEP(a, b) do {                                    \
            unsigned ka = fk[a], kb = fk[b];              \
            bool p = kb > ka;                             \
            fk[a] = p ? kb : ka;  fk[b] = p ? ka : kb;    \
            unsigned pa = pj[a], pb = pj[b];              \
            pj[a] = p ? pb : pa;  pj[b] = p ? pa : pb;    \
        } while (0)
        CEP(0,1); CEP(2,3); CEP(4,5); CEP(6,7);
        CEP(0,2); CEP(1,3); CEP(1,2);
        CEP(4,6); CEP(5,7); CEP(5,6);
        CEP(0,4); CEP(1,5); CEP(2,6); CEP(3,7);
        CEP(2,4); CEP(3,5);
        CEP(1,2); CEP(3,4); CEP(5,6);
#undef CEP
        unsigned pjpack = 0;
#pragma unroll
        for (int j = 0; j < 8; j++) pjpack |= pj[j] << (4 * j);

#pragma unroll
        for (int r = 0; r < TOPK; r++) {
            unsigned wb  = __reduce_max_sync(FULL, fk[0]);
            unsigned msk = __ballot_sync(FULL, fk[0] == wb);
            int src = __ffs(msk) - 1;

            int p0 = (int)(pjpack & 7u);
            int gg = 4 * lane + p0 + ((p0 & 4) ? 124 : 0);
            gg = __shfl_sync(FULL, gg, src);
            if (lane == r) g = gg;

            bool q = (lane == src);
            fk[0] = q ? fk[1] : fk[0];
            fk[1] = q ? fk[2] : fk[1];
            fk[2] = q ? fk[3] : fk[2];
            fk[3] = q ? fk[4] : fk[3];
            fk[4] = q ? fk[5] : fk[4];
            fk[5] = q ? fk[6] : fk[5];
            fk[6] = q ? fk[7] : fk[6];
            pjpack = q ? (pjpack >> 4) : pjpack;
        }
    }

    // epilogue on lanes 0..7: exact weight from (hot) logit reload, normalize, store
    if (lane < TOPK) {
        float x = __ldg(logits + (size_t)tok * NUM_E + g);
        float wgt = sigmoidf_fast(x);
        float sum = wgt;
#pragma unroll
        for (int off = 4; off; off >>= 1)
            sum += __shfl_xor_sync(0xFFu, sum, off);
        float wn = wgt * __fdividef(1.0f, sum + 1e-20f);

        out_idx[(size_t)tok * TOPK + lane] = (float)g;
        out_w [(size_t)tok * TOPK + lane] = wn;
    }
}

extern "C" void kernel_launch(void* const* d_in, const int* in_sizes, int n_in,
                              void* d_out, int out_size)
{
    const float* logits = (const float*)d_in[0];
    const float* bias   = (const float*)d_in[1];
    int T = in_sizes[0] / NUM_E;

    float* out_idx = (float*)d_out;
    float* out_w   = (float*)d_out + (size_t)T * TOPK;

    const int threads = 256;               // 8 warps = 8 tokens per block
    const int blocks  = (T + (threads / 32) - 1) / (threads / 32);
    moe_route_kernel<<<blocks, threads>>>(logits, bias, out_idx, out_w, T);
}

// round 9
// speedup vs baseline: 1.6876x; 1.0437x over previous
#include <cuda_runtime.h>

#define FULL 0xFFFFFFFFu
#define NUM_E 256
#define TOPK 8

// monotonic float -> u32 key (fallback path only)
__device__ __forceinline__ unsigned f2key(float f) {
    unsigned u = __float_as_uint(f);
    return u ^ ((unsigned)((int)u >> 31) | 0x80000000u);
}
__device__ __forceinline__ float sigmoidf_fast(float x) {
    return __fdividef(1.0f, 1.0f + __expf(-x));
}

__global__ void __launch_bounds__(256)
moe_route_kernel(const float* __restrict__ logits,
                 const float* __restrict__ bias,
                 float* __restrict__ out_idx,   // indices stored as float32 values
                 float* __restrict__ out_w,
                 int T)
{
    const int lane = threadIdx.x & 31;
    const int tok  = (int)((blockIdx.x * blockDim.x + threadIdx.x) >> 5);
    if (tok >= T) return;   // tok uniform per warp

    // coalesced row load: lane l covers experts {4l..4l+3, 128+4l..128+4l+3}
    const float4* row = reinterpret_cast<const float4*>(logits) + (size_t)tok * (NUM_E / 4);
    float4 x0 = row[lane];
    float4 x1 = row[lane + 32];
    const float4* b4 = reinterpret_cast<const float4*>(bias);
    float4 bb0 = __ldg(b4 + lane);
    float4 bb1 = __ldg(b4 + lane + 32);

    // ---- FAST PATH ----
    // key = raw float bits of (sigmoid+bias), low 8 bits replaced by the EXPERT
    // INDEX itself: g = 4*lane + (j&3) + 128*(j>>2) = (lane<<2)|Cj (disjoint bits).
    // Unique keys; decode is just (key & 255). Signed-int compare valid: top-9
    // keys always positive (~half the biases positive => 9th biased score >> 0).
    // Any 24-bit-prefix tie among adjacent winners -> exact fallback.
    int k[8];
    {
        float xs[8] = {x0.x, x0.y, x0.z, x0.w, x1.x, x1.y, x1.z, x1.w};
        float bs[8] = {bb0.x, bb0.y, bb0.z, bb0.w, bb1.x, bb1.y, bb1.z, bb1.w};
        const unsigned lane4 = (unsigned)lane << 2;
#pragma unroll
        for (int j = 0; j < 8; j++) {
            float s = sigmoidf_fast(xs[j]);
            unsigned ub  = __float_as_uint(s + bs[j]);
            unsigned fld = lane4 | (unsigned)((j & 3) | ((j >> 2) << 7));  // = expert idx
            k[j] = (int)((ub & 0xFFFFFF00u) | fld);
        }
    }

    // ---- sorted top-3 of each half (9 ops each), then merge to top-3-of-8 ----
    // top3of4(k0..k3): (0,1),(2,3) pair sorts; head=max(k0,k2); then
    // 2nd = max(k1, min(k0,k2)), 3rd = max(min(k1, min(k0,k2)), k3).
#define PAIR(a, b) { int hi = max(k[a], k[b]); int lo = min(k[a], k[b]); k[a] = hi; k[b] = lo; }
    PAIR(0,1) PAIR(2,3) PAIR(4,5) PAIR(6,7)
#undef PAIR
    int a0, a1, a2, b0, b1, b2;
    {
        int h = max(k[0], k[2]), t = min(k[0], k[2]);
        a0 = h;
        a1 = max(k[1], t);
        a2 = max(min(k[1], t), k[3]);
    }
    {
        int h = max(k[4], k[6]), t = min(k[4], k[6]);
        b0 = h;
        b1 = max(k[5], t);
        b2 = max(min(k[5], t), k[7]);
    }
    // top-3 of two sorted-3 lists: candidates c_i = max(a_i, b_{2-i}), then sort3
    int c0 = max(a0, b2);
    int c1 = max(a1, b1);
    int c2 = max(a2, b0);
    { int a = c0, b = c1; c0 = max(a, b); c1 = min(a, b); }
    { int a = c0, b = c2; c0 = max(a, b); c2 = min(a, b); }
    { int a = c1, b = c2; c1 = max(a, b); c2 = min(a, b); }

    // ---- 8 extraction rounds + 9th REDUX; verify interleaved in REDUX shadow ----
    // c2 never refilled: a lane's 4th win re-emits its 3rd value => adjacent
    // duplicate => mn < 256 => fallback.
    float f0 = __int_as_float(c0), f1 = __int_as_float(c1), f2 = __int_as_float(c2);
    int w[8];
    unsigned mn = 0xFFFFFFFFu;
    int prev = 0;
#pragma unroll
    for (int r = 0; r < TOPK; r++) {
        int wb = __reduce_max_sync(FULL, __float_as_int(f0));
        w[r] = wb;
        if (r > 0) mn = min(mn, (unsigned)(prev ^ wb));   // overlaps next REDUX
        prev = wb;
        bool own = (__float_as_int(f0) == wb);   // unique owner (expert id embedded)
        f0 = own ? f1 : f0;
        f1 = own ? f2 : f1;
    }
    {
        int w9 = __reduce_max_sync(FULL, __float_as_int(f0));   // 9th, for boundary check
        mn = min(mn, (unsigned)(prev ^ w9));
    }
    bool ok = (mn >= 256u);           // warp-uniform: all adjacent gaps >= 256 ulp-units

    int g = 0;
    if (ok) {
        // keep = w[lane] for lanes 0..7 via select tree (REDUX broadcast values)
        int s0 = (lane & 1) ? w[1] : w[0];
        int s1 = (lane & 1) ? w[3] : w[2];
        int s2 = (lane & 1) ? w[5] : w[4];
        int s3 = (lane & 1) ? w[7] : w[6];
        int u0 = (lane & 2) ? s1 : s0;
        int u1 = (lane & 2) ? s3 : s2;
        int keep = (lane & 4) ? u1 : u0;
        g = keep & 255;                          // expert index embedded directly
    } else {
        // ---- EXACT FALLBACK (rare, ~0.4%): full-precision keys, proven path ----
        float4 y0 = row[lane];        // L1/L2-hot reloads
        float4 y1 = row[lane + 32];
        float4 cb0 = __ldg(b4 + lane);
        float4 cb1 = __ldg(b4 + lane + 32);
        float ys[8] = {y0.x, y0.y, y0.z, y0.w, y1.x, y1.y, y1.z, y1.w};
        float cs[8] = {cb0.x, cb0.y, cb0.z, cb0.w, cb1.x, cb1.y, cb1.z, cb1.w};

        unsigned fk[8];
        unsigned pj[8];
#pragma unroll
        for (int j = 0; j < 8; j++) {
            float s = sigmoidf_fast(ys[j]);
            fk[j] = f2key(s + cs[j]);
            pj[j] = (unsigned)j;
        }
#define CEP(a, b) do {                                    \
            unsigned ka = fk[a], kb = fk[b];              \
            bool p = kb > ka;                             \
            fk[a] = p ? kb : ka;  fk[b] = p ? ka : kb;    \
            unsigned pa = pj[a], pb = pj[b];              \
            pj[a] = p ? pb : pa;  pj[b] = p ? pa : pb;    \
        } while (0)
        CEP(0,1); CEP(2,3); CEP(4,5); CEP(6,7);
        CEP(0,2); CEP(1,3); CEP(1,2);
        CEP(4,6); CEP(5,7); CEP(5,6);
        CEP(0,4); CEP(1,5); CEP(2,6); CEP(3,7);
        CEP(2,4); CEP(3,5);
        CEP(1,2); CEP(3,4); CEP(5,6);
#undef CEP
        unsigned pjpack = 0;
#pragma unroll
        for (int j = 0; j < 8; j++) pjpack |= pj[j] << (4 * j);

#pragma unroll
        for (int r = 0; r < TOPK; r++) {
            unsigned wb  = __reduce_max_sync(FULL, fk[0]);
            unsigned msk = __ballot_sync(FULL, fk[0] == wb);
            int src = __ffs(msk) - 1;

            int p0 = (int)(pjpack & 7u);
            int gg = 4 * lane + p0 + ((p0 & 4) ? 124 : 0);
            gg = __shfl_sync(FULL, gg, src);
            if (lane == r) g = gg;

            bool q = (lane == src);
            fk[0] = q ? fk[1] : fk[0];
            fk[1] = q ? fk[2] : fk[1];
            fk[2] = q ? fk[3] : fk[2];
            fk[3] = q ? fk[4] : fk[3];
            fk[4] = q ? fk[5] : fk[4];
            fk[5] = q ? fk[6] : fk[5];
            fk[6] = q ? fk[7] : fk[6];
            pjpack = q ? (pjpack >> 4) : pjpack;
        }
    }

    // epilogue on lanes 0..7: exact weight from (hot) logit reload, normalize, store
    if (lane < TOPK) {
        float x = __ldg(logits + (size_t)tok * NUM_E + g);
        float wgt = sigmoidf_fast(x);
        float sum = wgt;
#pragma unroll
        for (int off = 4; off; off >>= 1)
            sum += __shfl_xor_sync(0xFFu, sum, off);
        float wn = wgt * __fdividef(1.0f, sum + 1e-20f);

        out_idx[(size_t)tok * TOPK + lane] = (float)g;
        out_w [(size_t)tok * TOPK + lane] = wn;
    }
}

extern "C" void kernel_launch(void* const* d_in, const int* in_sizes, int n_in,
                              void* d_out, int out_size)
{
    const float* logits = (const float*)d_in[0];
    const float* bias   = (const float*)d_in[1];
    int T = in_sizes[0] / NUM_E;

    float* out_idx = (float*)d_out;
    float* out_w   = (float*)d_out + (size_t)T * TOPK;

    const int threads = 256;               // 8 warps = 8 tokens per block
    const int blocks  = (T + (threads / 32) - 1) / (threads / 32);
    moe_route_kernel<<<blocks, threads>>>(logits, bias, out_idx, out_w, T);
}